// round 14
// baseline (speedup 1.0000x reference)
#include <cuda_runtime.h>
#include <cstdint>

#define NUMEL        (8192 * 8192)            // 67,108,864
#define NGROUPS      (NUMEL / 4)              // 16,777,216 float4 groups
#define HALF_GROUPS  (NGROUPS / 2)            // codebook boundary
#define CB_ROWS      512                      // 2 codebooks * 256 centroids

#define TPB          512
#define JITER        2                        // groups per thread per iter
#define TILE_GROUPS  (TPB * JITER)            // 1024 groups = 16KB per tile
#define NTILES       (NGROUPS / TILE_GROUPS)  // 16384
#define GRID         (148 * 4)                // 592 persistent CTAs, 4/SM

__global__ __launch_bounds__(TPB, 4)          // 2048 thr/SM -> <=32 regs
void dequant_kernel(const float4* __restrict__ codebooks,   // 512 x float4 (8KB)
                    const float*  __restrict__ scales,      // NGROUPS/4 floats
                    const int*    __restrict__ codes,       // NGROUPS ints
                    float4*       __restrict__ out)         // NGROUPS float4
{
    __shared__ float4 scb[CB_ROWS];                 // 8KB codebook, only smem

    int t = threadIdx.x;
    scb[t] = codebooks[t];      // 512 threads -> one row each
    __syncthreads();            // the ONLY barrier in the kernel

    // ---- prologue: prefetch first tile's codes + scales ----
    unsigned int tile = blockIdx.x;
    int   c0, c1;
    float s0, s1;
    {
        unsigned int gbase = tile * TILE_GROUPS;
        c0 = __ldg(&codes[gbase + (unsigned)t]);
        c1 = __ldg(&codes[gbase + TPB + (unsigned)t]);
        s0 = __ldg(&scales[(gbase + (unsigned)t) >> 4]);
        s1 = __ldg(&scales[(gbase + TPB + (unsigned)t) >> 4]);
    }

    for (; tile < NTILES; tile += GRID) {
        unsigned int gbase = tile * TILE_GROUPS;
        // 1024-group tile never straddles the codebook-half boundary.
        const float4* cb = scb + ((gbase >= HALF_GROUPS) ? 256 : 0);

        // Gather current tile into registers (consumes prefetched c/s).
        float4 v0 = cb[c0];
        float4 v1 = cb[c1];
        float a0 = s0, a1 = s1;

        // Prefetch NEXT tile's codes/scales — overlaps gather + stores.
        unsigned int ntile = tile + GRID;
        if (ntile < NTILES) {
            unsigned int nbase = ntile * TILE_GROUPS;
            c0 = __ldg(&codes[nbase + (unsigned)t]);
            c1 = __ldg(&codes[nbase + TPB + (unsigned)t]);
            s0 = __ldg(&scales[(nbase + (unsigned)t) >> 4]);
            s1 = __ldg(&scales[(nbase + TPB + (unsigned)t) >> 4]);
        }

        v0.x *= a0; v0.y *= a0; v0.z *= a0; v0.w *= a0;
        v1.x *= a1; v1.y *= a1; v1.z *= a1; v1.w *= a1;

        // Direct coalesced streaming stores — no staging, no barriers.
        __stcs(out + gbase + (unsigned)t,        v0);
        __stcs(out + gbase + TPB + (unsigned)t,  v1);
    }
}

extern "C" void kernel_launch(void* const* d_in, const int* in_sizes, int n_in,
                              void* d_out, int out_size)
{
    const float4* codebooks = (const float4*)d_in[0];  // [2,256,4] fp32
    const float*  scales    = (const float*) d_in[1];  // [numel/64, 1] fp32
    const int*    codes     = (const int*)   d_in[2];  // [2, numel/8] int32 flat
    float4*       out       = (float4*)d_out;          // [8192, 8192] fp32

    dequant_kernel<<<GRID, TPB>>>(codebooks, scales, codes, out);
}